// round 16
// baseline (speedup 1.0000x reference)
#include <cuda_runtime.h>
#include <cuda_bf16.h>
#include <cuda_fp16.h>
#include <mma.h>
#include <cstdint>

using namespace nvcuda;

#define NP   8192
#define FD   128
#define C0N  256
#define C1N  128
#define BN_EPS 1e-3f
#define KSPLIT 4
#define KQ (NP / KSPLIT)   // 2048

// ---------------- cp.async helpers ------------------------------------------
__device__ __forceinline__ void cp16(void* dst_smem, const void* src) {
    unsigned int d = (unsigned int)__cvta_generic_to_shared(dst_smem);
    asm volatile("cp.async.cg.shared.global [%0], [%1], 16;\n" :: "r"(d), "l"(src));
}
__device__ __forceinline__ void cp_commit() { asm volatile("cp.async.commit_group;\n"); }
template <int N> __device__ __forceinline__ void cp_wait() {
    asm volatile("cp.async.wait_group %0;\n" :: "n"(N));
}

// ---------------- scratch (device globals; no allocation allowed) -----------
__device__ __align__(16) __half d_Adjh[(size_t)NP * NP]; // fp16 adj (exact 0/1)
__device__ __align__(16) __half d_Xf[NP * FD];           // fp16(X)
__device__ __align__(16) float  d_deg[NP];
__device__ __align__(16) float  d_Rp[KSPLIT][NP * FD];   // Rpre partials
__device__ __align__(16) __half d_RpH[NP * FD];          // hi(sum Rp)
__device__ __align__(16) __half d_RpL[NP * FD];          // lo(...)
__device__ __align__(16) __half d_K1h[FD * C0N];
__device__ __align__(16) __half d_K1l[FD * C0N];
__device__ __align__(16) __half d_K2f[C0N * C1N];
__device__ __align__(16) float  d_H[NP * C0N];
__device__ __align__(16) __half d_R2f[NP * C1N];         // fp16(Rs@K2), 4096-scaled
__device__ __align__(16) float  d_Op[KSPLIT][NP * C1N];  // O partials
__device__ __align__(16) float  d_O[NP * C1N];
__device__ float d_sum1[C0N], d_sq1[C0N];
__device__ float d_sum2[C1N], d_sq2[C1N];
__device__ int   d_cnt1[32], d_cnt2[32];                 // arrival counters

// ---- prep: adj int32 -> fp16, FUSED column-degree (128x128 tiles) ----------
__global__ void __launch_bounds__(256) k_prep_adj(const int* __restrict__ adj) {
    __shared__ float dred[8][128];
    const int r0 = blockIdx.x * 128;
    const int k0 = blockIdx.y * 128;
    const int tid = threadIdx.x;
    const int c4 = (tid & 31) * 4;
    const int rb = tid >> 5;

    float dreg[4] = {0.f, 0.f, 0.f, 0.f};
#pragma unroll
    for (int s = 0; s < 16; s++) {
        int kl = rb + s * 8;
        int4 a = *(const int4*)(adj + (size_t)(k0 + kl) * NP + r0 + c4);
        __half o[4];
        o[0] = __float2half_rn((float)a.x);
        o[1] = __float2half_rn((float)a.y);
        o[2] = __float2half_rn((float)a.z);
        o[3] = __float2half_rn((float)a.w);
        *(uint2*)(d_Adjh + (size_t)(k0 + kl) * NP + r0 + c4) = *(uint2*)o;
        dreg[0] += (float)a.x;
        dreg[1] += (float)a.y;
        dreg[2] += (float)a.z;
        dreg[3] += (float)a.w;
    }
#pragma unroll
    for (int j = 0; j < 4; j++) dred[rb][c4 + j] = dreg[j];
    __syncthreads();
    if (tid < 128) {
        float s = 0.f;
#pragma unroll
        for (int g = 0; g < 8; g++) s += dred[g][tid];
        atomicAdd(&d_deg[r0 + tid], s);
    }
}

// -- prep: X -> fp16; zero sums/deg/counters; K1 -> hi/lo; K2 -> fp16 ---------
__global__ void __launch_bounds__(256) k_prep_x(const float* __restrict__ X,
                                                const float* __restrict__ K1,
                                                const float* __restrict__ K2) {
    const int tid = threadIdx.x;
    if (blockIdx.x == 0) {
        if (tid < C0N) { d_sum1[tid] = 0.f; d_sq1[tid] = 0.f; }
        if (tid < C1N) { d_sum2[tid] = 0.f; d_sq2[tid] = 0.f; }
    }
    if (blockIdx.x == 1 && tid < 32) { d_cnt1[tid] = 0; d_cnt2[tid] = 0; }
    if (tid < 8) d_deg[blockIdx.x * 8 + tid] = 0.f;

    if (blockIdx.x < 32) {                       // K1: 32768 elems
        size_t i = ((size_t)blockIdx.x * 256 + tid) * 4;
        float4 v = *(const float4*)(K1 + i);
        float vv[4] = {v.x, v.y, v.z, v.w};
        __half h[4], l[4];
#pragma unroll
        for (int j = 0; j < 4; j++) {
            h[j] = __float2half_rn(vv[j]);
            l[j] = __float2half_rn(vv[j] - __half2float(h[j]));
        }
        *(uint2*)(d_K1h + i) = *(uint2*)h;
        *(uint2*)(d_K1l + i) = *(uint2*)l;
    } else if (blockIdx.x < 64) {                // K2: 32768 elems
        size_t i = ((size_t)(blockIdx.x - 32) * 256 + tid) * 4;
        float4 v = *(const float4*)(K2 + i);
        __half h[4];
        h[0] = __float2half_rn(v.x);
        h[1] = __float2half_rn(v.y);
        h[2] = __float2half_rn(v.z);
        h[3] = __float2half_rn(v.w);
        *(uint2*)(d_K2f + i) = *(uint2*)h;
    }

    size_t i = ((size_t)blockIdx.x * 256 + tid) * 4;
    float4 x = *(const float4*)(X + i);
    __half h[4];
    h[0] = __float2half_rn(x.x);
    h[1] = __float2half_rn(x.y);
    h[2] = __float2half_rn(x.z);
    h[3] = __float2half_rn(x.w);
    *(uint2*)(d_Xf + i) = *(uint2*)h;
}

// ============================================================================
// GEMM1: Rp[q] = A^T @ X over K quarter q. grid (32, 4). CTA 256x128, BK=64.
// FUSED epilogue: last CTA of the 4 quarters sums partials -> RpH/RpL.
// ============================================================================
#define G1_LDA 264
#define G1_LDX 136
#define G1_AS_BYTES (2 * 64 * G1_LDA * 2)
#define G1_SMEM     (G1_AS_BYTES + 2 * 64 * G1_LDX * 2) // 102400

__global__ void __launch_bounds__(256) k_gemm1() {
    extern __shared__ __align__(16) char smem_raw[];
    __half (*As)[64][G1_LDA] = (__half(*)[64][G1_LDA])smem_raw;
    __half (*Xs)[64][G1_LDX] = (__half(*)[64][G1_LDX])(smem_raw + G1_AS_BYTES);
    __shared__ int is_last;

    const int r0    = blockIdx.x * 256;
    const int kbase = blockIdx.y * KQ;
    const int tid   = threadIdx.x;
    const int warp  = tid >> 5;
    const int wm    = warp & 3;
    const int wn    = warp >> 2;

    wmma::fragment<wmma::accumulator, 16, 16, 16, float> acc[4][4];
#pragma unroll
    for (int i = 0; i < 4; i++)
#pragma unroll
        for (int j = 0; j < 4; j++) wmma::fill_fragment(acc[i][j], 0.0f);

    {
#pragma unroll
        for (int s = 0; s < 8; s++) {
            int u = tid + s * 256, kk = u >> 5, rr = (u & 31) * 8;
            cp16(&As[0][kk][rr], d_Adjh + (size_t)(kbase + kk) * NP + r0 + rr);
        }
#pragma unroll
        for (int s = 0; s < 4; s++) {
            int u = tid + s * 256, kk = u >> 4, cc = (u & 15) * 8;
            cp16(&Xs[0][kk][cc], d_Xf + (size_t)(kbase + kk) * FD + cc);
        }
        cp_commit();
    }

    const int T = KQ / 64;
    for (int t = 0; t < T; t++) {
        const int buf = t & 1;
        if (t + 1 < T) {
            const int nb = buf ^ 1;
            const int k1 = kbase + (t + 1) * 64;
#pragma unroll
            for (int s = 0; s < 8; s++) {
                int u = tid + s * 256, kk = u >> 5, rr = (u & 31) * 8;
                cp16(&As[nb][kk][rr], d_Adjh + (size_t)(k1 + kk) * NP + r0 + rr);
            }
#pragma unroll
            for (int s = 0; s < 4; s++) {
                int u = tid + s * 256, kk = u >> 4, cc = (u & 15) * 8;
                cp16(&Xs[nb][kk][cc], d_Xf + (size_t)(k1 + kk) * FD + cc);
            }
            cp_commit();
            cp_wait<1>();
        } else {
            cp_wait<0>();
        }
        __syncthreads();

#pragma unroll
        for (int ks = 0; ks < 4; ks++) {
            wmma::fragment<wmma::matrix_a, 16, 16, 16, __half, wmma::col_major> af[4];
#pragma unroll
            for (int i = 0; i < 4; i++)
                wmma::load_matrix_sync(af[i], &As[buf][ks * 16][wm * 64 + i * 16], G1_LDA);
#pragma unroll
            for (int j = 0; j < 4; j++) {
                wmma::fragment<wmma::matrix_b, 16, 16, 16, __half, wmma::row_major> bf;
                wmma::load_matrix_sync(bf, &Xs[buf][ks * 16][wn * 64 + j * 16], G1_LDX);
#pragma unroll
                for (int i = 0; i < 4; i++) wmma::mma_sync(acc[i][j], af[i], bf, acc[i][j]);
            }
        }
        __syncthreads();
    }

    float* dst = d_Rp[blockIdx.y];
#pragma unroll
    for (int i = 0; i < 4; i++)
#pragma unroll
        for (int j = 0; j < 4; j++)
            wmma::store_matrix_sync(&dst[(size_t)(r0 + wm * 64 + i * 16) * FD + wn * 64 + j * 16],
                                    acc[i][j], FD, wmma::mem_row_major);

    // fused prep_rpre: last of the 4 K-quarter CTAs sums + splits hi/lo
    __threadfence();
    __syncthreads();
    if (tid == 0) is_last = (atomicAdd(&d_cnt1[blockIdx.x], 1) == KSPLIT - 1);
    __syncthreads();
    if (is_last) {
        __threadfence();
        const size_t base = (size_t)r0 * FD;   // 256*128 = 32768 contiguous floats
#pragma unroll 4
        for (int s = 0; s < 32; s++) {
            size_t i = base + ((size_t)tid + s * 256) * 4;
            float4 a = *(const float4*)(d_Rp[0] + i);
            float4 b = *(const float4*)(d_Rp[1] + i);
            float4 c = *(const float4*)(d_Rp[2] + i);
            float4 d = *(const float4*)(d_Rp[3] + i);
            float vv[4] = {a.x + b.x + c.x + d.x, a.y + b.y + c.y + d.y,
                           a.z + b.z + c.z + d.z, a.w + b.w + c.w + d.w};
            __half h[4], l[4];
#pragma unroll
            for (int j = 0; j < 4; j++) {
                h[j] = __float2half_rn(vv[j]);
                l[j] = __float2half_rn(vv[j] - __half2float(h[j]));
            }
            *(uint2*)(d_RpH + i) = *(uint2*)h;
            *(uint2*)(d_RpL + i) = *(uint2*)l;
        }
    }
}

// ============================================================================
// GEMM3: Op[q] = A @ R2f over K quarter q. grid (32, 4). CTA 256x128, BK=64.
// FUSED epilogue: last CTA combines partials + bias -> d_O + BN2 stats.
// ============================================================================
#define G3_LDA 72
#define G3_LDB 136
#define G3_AS_BYTES (2 * 256 * G3_LDA * 2)
#define G3_SMEM     (G3_AS_BYTES + 2 * 64 * G3_LDB * 2) // 108544

__global__ void __launch_bounds__(256) k_gemm3(const float* __restrict__ bias2) {
    extern __shared__ __align__(16) char smem_raw[];
    __half (*As)[256][G3_LDA] = (__half(*)[256][G3_LDA])smem_raw;
    __half (*Bs)[64][G3_LDB]  = (__half(*)[64][G3_LDB])(smem_raw + G3_AS_BYTES);
    __shared__ int is_last;

    const int p0    = blockIdx.x * 256;
    const int kbase = blockIdx.y * KQ;
    const int tid   = threadIdx.x;
    const int warp  = tid >> 5;
    const int wm    = warp & 3;
    const int wn    = warp >> 2;

    wmma::fragment<wmma::accumulator, 16, 16, 16, float> acc[4][4];
#pragma unroll
    for (int i = 0; i < 4; i++)
#pragma unroll
        for (int j = 0; j < 4; j++) wmma::fill_fragment(acc[i][j], 0.0f);

    {
#pragma unroll
        for (int s = 0; s < 8; s++) {
            int u = tid + s * 256, pp = u >> 3, kc = (u & 7) * 8;
            cp16(&As[0][pp][kc], d_Adjh + (size_t)(p0 + pp) * NP + kbase + kc);
        }
#pragma unroll
        for (int s = 0; s < 4; s++) {
            int u = tid + s * 256, kk = u >> 4, cc = (u & 15) * 8;
            cp16(&Bs[0][kk][cc], d_R2f + (size_t)(kbase + kk) * C1N + cc);
        }
        cp_commit();
    }

    const int T = KQ / 64;
    for (int t = 0; t < T; t++) {
        const int buf = t & 1;
        if (t + 1 < T) {
            const int nb = buf ^ 1;
            const int k1 = kbase + (t + 1) * 64;
#pragma unroll
            for (int s = 0; s < 8; s++) {
                int u = tid + s * 256, pp = u >> 3, kc = (u & 7) * 8;
                cp16(&As[nb][pp][kc], d_Adjh + (size_t)(p0 + pp) * NP + k1 + kc);
            }
#pragma unroll
            for (int s = 0; s < 4; s++) {
                int u = tid + s * 256, kk = u >> 4, cc = (u & 15) * 8;
                cp16(&Bs[nb][kk][cc], d_R2f + (size_t)(k1 + kk) * C1N + cc);
            }
            cp_commit();
            cp_wait<1>();
        } else {
            cp_wait<0>();
        }
        __syncthreads();

#pragma unroll
        for (int ks = 0; ks < 4; ks++) {
            wmma::fragment<wmma::matrix_a, 16, 16, 16, __half, wmma::row_major> af[4];
#pragma unroll
            for (int i = 0; i < 4; i++)
                wmma::load_matrix_sync(af[i], &As[buf][wm * 64 + i * 16][ks * 16], G3_LDA);
#pragma unroll
            for (int j = 0; j < 4; j++) {
                wmma::fragment<wmma::matrix_b, 16, 16, 16, __half, wmma::row_major> bf;
                wmma::load_matrix_sync(bf, &Bs[buf][ks * 16][wn * 64 + j * 16], G3_LDB);
#pragma unroll
                for (int i = 0; i < 4; i++) wmma::mma_sync(acc[i][j], af[i], bf, acc[i][j]);
            }
        }
        __syncthreads();
    }

    float* dst = d_Op[blockIdx.y];
#pragma unroll
    for (int i = 0; i < 4; i++)
#pragma unroll
        for (int j = 0; j < 4; j++)
            wmma::store_matrix_sync(&dst[(size_t)(p0 + wm * 64 + i * 16) * C1N + wn * 64 + j * 16],
                                    acc[i][j], C1N, wmma::mem_row_major);

    // fused stats2: last CTA combines partials + bias, writes O, BN2 stats
    __threadfence();
    __syncthreads();
    if (tid == 0) is_last = (atomicAdd(&d_cnt2[blockIdx.x], 1) == KSPLIT - 1);
    __syncthreads();
    if (is_last) {
        __threadfence();
        const int c    = tid & 127;
        const int half = tid >> 7;
        const float b  = bias2[c];
        const float inv = 1.0f / 4096.0f;
        float s = 0.f, q = 0.f;
#pragma unroll 4
        for (int r = p0 + half * 128; r < p0 + half * 128 + 128; r++) {
            size_t idx = (size_t)r * C1N + c;
            float v = (d_Op[0][idx] + d_Op[1][idx] + d_Op[2][idx] + d_Op[3][idx]) * inv + b;
            d_O[idx] = v;
            s += v;
            q = fmaf(v, v, q);
        }
        atomicAdd(&d_sum2[c], s);
        atomicAdd(&d_sq2[c], q);
    }
}

// ============================================================================
// small_h (tensor, 3-term hi/lo): H = invdeg*(Rp@K1)+b1, fused BN1 stats.
// grid (128, 2): M-tile 64, N-tile 128, K=128 single shot.
// ============================================================================
#define SH_LDA 136
#define SH_LDB 136
#define SH_A_BYTES (64 * SH_LDA * 2)
#define SH_B_BYTES (128 * SH_LDB * 2)
#define SH_SMEM    (2 * SH_A_BYTES + 2 * SH_B_BYTES)   // 104448
#define SH_LDC 132

__global__ void __launch_bounds__(256) k_small_h_tc(const float* __restrict__ bias) {
    extern __shared__ __align__(16) char sm[];
    __half (*Ah)[SH_LDA] = (__half(*)[SH_LDA])sm;
    __half (*Al)[SH_LDA] = (__half(*)[SH_LDA])(sm + SH_A_BYTES);
    __half (*Bh)[SH_LDB] = (__half(*)[SH_LDB])(sm + 2 * SH_A_BYTES);
    __half (*Bl)[SH_LDB] = (__half(*)[SH_LDB])(sm + 2 * SH_A_BYTES + SH_B_BYTES);
    float  (*Ct)[SH_LDC] = (float(*)[SH_LDC])sm;

    const int m0  = blockIdx.x * 64;
    const int n0  = blockIdx.y * 128;
    const int tid = threadIdx.x;
    const int warp = tid >> 5;
    const int wm   = warp & 1;
    const int wn   = warp >> 1;

#pragma unroll
    for (int s = 0; s < 4; s++) {
        int u = tid + s * 256, row = u >> 4, col = (u & 15) * 8;
        cp16(&Ah[row][col], d_RpH + (size_t)(m0 + row) * FD + col);
        cp16(&Al[row][col], d_RpL + (size_t)(m0 + row) * FD + col);
    }
#pragma unroll
    for (int s = 0; s < 8; s++) {
        int u = tid + s * 256, kk = u >> 4, cc = (u & 15) * 8;
        cp16(&Bh[kk][cc], d_K1h + (size_t)kk * C0N + n0 + cc);
        cp16(&Bl[kk][cc], d_K1l + (size_t)kk * C0N + n0 + cc);
    }
    cp_commit();
    cp_wait<0>();
    __syncthreads();

    wmma::fragment<wmma::accumulator, 16, 16, 16, float> acc[2][2];
#pragma unroll
    for (int i = 0; i < 2; i++)
#pragma unroll
        for (int j = 0; j < 2; j++) wmma::fill_fragment(acc[i][j], 0.0f);

#pragma unroll
    for (int ks = 0; ks < 8; ks++) {
        wmma::fragment<wmma::matrix_a, 16, 16, 16, __half, wmma::row_major> afh[2], afl[2];
#pragma unroll
        for (int i = 0; i < 2; i++) {
            wmma::load_matrix_sync(afh[i], &Ah[wm * 32 + i * 16][ks * 16], SH_LDA);
            wmma::load_matrix_sync(afl[i], &Al[wm * 32 + i * 16][ks * 16], SH_LDA);
        }
        wmma::fragment<wmma::matrix_b, 16, 16, 16, __half, wmma::row_major> bfh[2], bfl[2];
#pragma unroll
        for (int j = 0; j < 2; j++) {
            wmma::load_matrix_sync(bfh[j], &Bh[ks * 16][wn * 32 + j * 16], SH_LDB);
            wmma::load_matrix_sync(bfl[j], &Bl[ks * 16][wn * 32 + j * 16], SH_LDB);
        }
#pragma unroll
        for (int j = 0; j < 2; j++)
#pragma unroll
            for (int i = 0; i < 2; i++) {
                wmma::mma_sync(acc[i][j], afh[i], bfh[j], acc[i][j]);
                wmma::mma_sync(acc[i][j], afh[i], bfl[j], acc[i][j]);
                wmma::mma_sync(acc[i][j], afl[i], bfh[j], acc[i][j]);
            }
    }
    __syncthreads();

#pragma unroll
    for (int i = 0; i < 2; i++)
#pragma unroll
        for (int j = 0; j < 2; j++)
            wmma::store_matrix_sync(&Ct[wm * 32 + i * 16][wn * 32 + j * 16],
                                    acc[i][j], SH_LDC, wmma::mem_row_major);
    __syncthreads();

    {
        const int c    = tid & 127;
        const int half = tid >> 7;
        const float b  = bias[n0 + c];
        float s = 0.f, q = 0.f;
#pragma unroll 8
        for (int r = half * 32; r < half * 32 + 32; r++) {
            int gr = m0 + r;
            float dg = d_deg[gr];
            float idg = (dg > 0.5f) ? (1.0f / dg) : 0.0f;
            float v = Ct[r][c] * idg + b;
            d_H[(size_t)gr * C0N + n0 + c] = v;
            s += v;
            q = fmaf(v, v, q);
        }
        atomicAdd(&d_sum1[n0 + c], s);
        atomicAdd(&d_sq1[n0 + c], q);
    }
}

// ============================================================================
// small_r2 (tensor, fused fin1 + affine-on-load): R2f = fp16(4096*invdeg*
// BN1(H)) @ K2f.  grid 128: M-tile 64, N=128 full, K=256 single shot.
// ============================================================================
#define SR_LDA 264
#define SR_LDB 136
#define SR_A_BYTES (64 * SR_LDA * 2)
#define SR_B_BYTES (256 * SR_LDB * 2)
#define SR_SMEM    (SR_A_BYTES + SR_B_BYTES)   // 103424
#define SR_LDC 132

__global__ void __launch_bounds__(256) k_small_r2_tc(const float* __restrict__ gamma,
                                                     const float* __restrict__ beta) {
    extern __shared__ __align__(16) char sm[];
    __half (*As)[SR_LDA] = (__half(*)[SR_LDA])sm;
    __half (*Bs)[SR_LDB] = (__half(*)[SR_LDB])(sm + SR_A_BYTES);
    float  (*Ct)[SR_LDC] = (float(*)[SR_LDC])sm;
    __shared__ float ssc[C0N], ssh[C0N], sidg[64];

    const int m0  = blockIdx.x * 64;
    const int tid = threadIdx.x;
    const int warp = tid >> 5;
    const int wm   = warp & 1;
    const int wn   = warp >> 1;

    // B tile via cp.async (issue first, overlaps with fin1 + A affine)
#pragma unroll
    for (int s = 0; s < 16; s++) {
        int u = tid + s * 256, kk = u >> 4, cc = (u & 15) * 8;
        cp16(&Bs[kk][cc], d_K2f + (size_t)kk * C1N + cc);
    }
    cp_commit();

    // fin1 (redundant per block, cheap) + per-row scaled invdeg
    {
        float mean = d_sum1[tid] * (1.0f / NP);
        float var  = d_sq1[tid] * (1.0f / NP) - mean * mean;
        float sc   = gamma[tid] * rsqrtf(var + BN_EPS);
        ssc[tid] = sc;
        ssh[tid] = beta[tid] - mean * sc;
    }
    if (tid < 64) {
        float dg = d_deg[m0 + tid];
        sidg[tid] = (dg > 0.5f) ? (4096.0f / dg) : 0.0f;
    }
    __syncthreads();

    // A tile: LDG H fp32 -> affine*idg -> fp16 -> STS (64 rows x 256 cols)
#pragma unroll
    for (int s = 0; s < 16; s++) {
        int u = tid + s * 256, row = u >> 6, col = (u & 63) * 4;
        float4 h4 = *(const float4*)(d_H + (size_t)(m0 + row) * C0N + col);
        float idg = sidg[row];
        __half o[4];
        o[0] = __float2half_rn(idg * fmaf(h4.x, ssc[col + 0], ssh[col + 0]));
        o[1] = __float2half_rn(idg * fmaf(h4.y, ssc[col + 1], ssh[col + 1]));
        o[2] = __float2half_rn(idg * fmaf(h4.z, ssc[col + 2], ssh[col + 2]));
        o[3] = __float2half_rn(idg * fmaf(h4.w, ssc[col + 3], ssh[col + 3]));
        *(uint2*)&As[row][col] = *(uint2*)o;
    }
    cp_wait<0>();
    __syncthreads();

    wmma::fragment<wmma::accumulator, 16, 16, 16, float> acc[2][2];
#pragma unroll
    for (int i = 0; i < 2; i++)
#pragma unroll
        for (int j = 0; j < 2; j++) wmma::fill_fragment(acc[i][j], 0.0f);

#pragma unroll
    for (int ks = 0; ks < 16; ks++) {
        wmma::fragment<wmma::matrix_a, 16, 16, 16, __half, wmma::row_major> af[2];
#pragma unroll
        for (int i = 0; i < 2; i++)
            wmma::load_matrix_sync(af[i], &As[wm * 32 + i * 16][ks * 16], SR_LDA);
        wmma::fragment<wmma::matrix_b, 16, 16, 16, __half, wmma::row_major> bf[2];
#pragma unroll
        for (int j = 0; j < 2; j++)
            wmma::load_matrix_sync(bf[j], &Bs[ks * 16][wn * 32 + j * 16], SR_LDB);
#pragma unroll
        for (int j = 0; j < 2; j++)
#pragma unroll
            for (int i = 0; i < 2; i++) wmma::mma_sync(acc[i][j], af[i], bf[j], acc[i][j]);
    }
    __syncthreads();

#pragma unroll
    for (int i = 0; i < 2; i++)
#pragma unroll
        for (int j = 0; j < 2; j++)
            wmma::store_matrix_sync(&Ct[wm * 32 + i * 16][wn * 32 + j * 16],
                                    acc[i][j], SR_LDC, wmma::mem_row_major);
    __syncthreads();

    {
        const int c    = tid & 127;
        const int half = tid >> 7;
#pragma unroll 8
        for (int r = half * 32; r < half * 32 + 32; r++)
            d_R2f[(size_t)(m0 + r) * C1N + c] = __float2half_rn(Ct[r][c]);
    }
}

// ---------------- output with fin2 inlined -----------------------------------
__global__ void __launch_bounds__(256) k_out(const float* __restrict__ gamma,
                                             const float* __restrict__ beta,
                                             float* __restrict__ out) {
    __shared__ float ssc[C1N], ssh[C1N];
    const int tid = threadIdx.x;
    if (tid < C1N) {
        float mean = d_sum2[tid] * (1.0f / NP);
        float var  = d_sq2[tid] * (1.0f / NP) - mean * mean;
        float sc   = gamma[tid] * rsqrtf(var + BN_EPS);
        ssc[tid] = sc;
        ssh[tid] = beta[tid] - mean * sc;
    }
    __syncthreads();
    size_t i = ((size_t)blockIdx.x * 256 + tid) * 4;
    int c = (int)(i & (C1N - 1));
    float4 v = *(const float4*)(d_O + i);
    float4 o;
    o.x = fmaf(v.x, ssc[c + 0], ssh[c + 0]);
    o.y = fmaf(v.y, ssc[c + 1], ssh[c + 1]);
    o.z = fmaf(v.z, ssc[c + 2], ssh[c + 2]);
    o.w = fmaf(v.w, ssc[c + 3], ssh[c + 3]);
    *(float4*)(out + i) = o;
}

// ---------------- launch ----------------------------------------------------
extern "C" void kernel_launch(void* const* d_in, const int* in_sizes, int n_in,
                              void* d_out, int out_size) {
    const float* features = (const float*)d_in[0];
    const int*   adj      = (const int*)d_in[1];
    const float* kernel_1 = (const float*)d_in[2];
    const float* bias_1   = (const float*)d_in[3];
    const float* gamma_1  = (const float*)d_in[4];
    const float* beta_1   = (const float*)d_in[5];
    const float* kernel_2 = (const float*)d_in[6];
    const float* bias_2   = (const float*)d_in[7];
    const float* gamma_2  = (const float*)d_in[8];
    const float* beta_2   = (const float*)d_in[9];
    float* out = (float*)d_out;

    cudaFuncSetAttribute(k_gemm1, cudaFuncAttributeMaxDynamicSharedMemorySize, G1_SMEM);
    cudaFuncSetAttribute(k_gemm3, cudaFuncAttributeMaxDynamicSharedMemorySize, G3_SMEM);
    cudaFuncSetAttribute(k_small_h_tc, cudaFuncAttributeMaxDynamicSharedMemorySize, SH_SMEM);
    cudaFuncSetAttribute(k_small_r2_tc, cudaFuncAttributeMaxDynamicSharedMemorySize, SR_SMEM);

    k_prep_x<<<NP * FD / (256 * 4), 256>>>(features, kernel_1, kernel_2); // X/K1/K2 + zero
    k_prep_adj<<<dim3(NP / 128, NP / 128), 256>>>(adj);                   // adj fp16 + degree
    k_gemm1<<<dim3(NP / 256, KSPLIT), 256, G1_SMEM>>>();                  // Rpre + fused sum/split
    k_small_h_tc<<<dim3(NP / 64, C0N / 128), 256, SH_SMEM>>>(bias_1);     // H + stats1
    k_small_r2_tc<<<NP / 64, 256, SR_SMEM>>>(gamma_1, beta_1);            // fin1 + Rs + R2f
    k_gemm3<<<dim3(NP / 256, KSPLIT), 256, G3_SMEM>>>(bias_2);            // O + fused stats2
    k_out<<<NP * C1N / (256 * 4), 256>>>(gamma_2, beta_2, out);           // fin2 + out
}

// round 17
// speedup vs baseline: 1.1204x; 1.1204x over previous
#include <cuda_runtime.h>
#include <cuda_bf16.h>
#include <cuda_fp16.h>
#include <mma.h>
#include <cstdint>

using namespace nvcuda;

#define NP   8192
#define FD   128
#define C0N  256
#define C1N  128
#define BN_EPS 1e-3f
#define KSPLIT 4
#define KQ (NP / KSPLIT)   // 2048

// ---------------- cp.async helpers ------------------------------------------
__device__ __forceinline__ void cp16(void* dst_smem, const void* src) {
    unsigned int d = (unsigned int)__cvta_generic_to_shared(dst_smem);
    asm volatile("cp.async.cg.shared.global [%0], [%1], 16;\n" :: "r"(d), "l"(src));
}
__device__ __forceinline__ void cp_commit() { asm volatile("cp.async.commit_group;\n"); }
template <int N> __device__ __forceinline__ void cp_wait() {
    asm volatile("cp.async.wait_group %0;\n" :: "n"(N));
}

// ---------------- scratch (device globals; no allocation allowed) -----------
__device__ __align__(16) __half d_Adjh[(size_t)NP * NP]; // fp16 adj (exact 0/1)
__device__ __align__(16) __half d_Xf[NP * FD];           // fp16(X)
__device__ __align__(16) float  d_deg[NP];
__device__ __align__(16) float  d_Rp[KSPLIT][NP * FD];   // Rpre partials
__device__ __align__(16) __half d_RpH[NP * FD];          // hi(sum Rp)
__device__ __align__(16) __half d_RpL[NP * FD];          // lo(...)
__device__ __align__(16) __half d_K1h[FD * C0N];
__device__ __align__(16) __half d_K1l[FD * C0N];
__device__ __align__(16) __half d_K2f[C0N * C1N];
__device__ __align__(16) float  d_H[NP * C0N];
__device__ __align__(16) __half d_R2f[NP * C1N];         // fp16(Rs@K2), 4096-scaled
__device__ __align__(16) float  d_Op[KSPLIT][NP * C1N];  // O partials
__device__ __align__(16) float  d_O[NP * C1N];
__device__ float d_sum1[C0N], d_sq1[C0N];
__device__ float d_sum2[C1N], d_sq2[C1N];

// ---- prep: adj int32 -> fp16, FUSED column-degree (128x128 tiles) ----------
__global__ void __launch_bounds__(256) k_prep_adj(const int* __restrict__ adj) {
    __shared__ float dred[8][128];
    const int r0 = blockIdx.x * 128;
    const int k0 = blockIdx.y * 128;
    const int tid = threadIdx.x;
    const int c4 = (tid & 31) * 4;
    const int rb = tid >> 5;

    float dreg[4] = {0.f, 0.f, 0.f, 0.f};
#pragma unroll
    for (int s = 0; s < 16; s++) {
        int kl = rb + s * 8;
        int4 a = *(const int4*)(adj + (size_t)(k0 + kl) * NP + r0 + c4);
        __half o[4];
        o[0] = __float2half_rn((float)a.x);
        o[1] = __float2half_rn((float)a.y);
        o[2] = __float2half_rn((float)a.z);
        o[3] = __float2half_rn((float)a.w);
        *(uint2*)(d_Adjh + (size_t)(k0 + kl) * NP + r0 + c4) = *(uint2*)o;
        dreg[0] += (float)a.x;
        dreg[1] += (float)a.y;
        dreg[2] += (float)a.z;
        dreg[3] += (float)a.w;
    }
#pragma unroll
    for (int j = 0; j < 4; j++) dred[rb][c4 + j] = dreg[j];
    __syncthreads();
    if (tid < 128) {
        float s = 0.f;
#pragma unroll
        for (int g = 0; g < 8; g++) s += dred[g][tid];
        atomicAdd(&d_deg[r0 + tid], s);
    }
}

// -- prep: X -> fp16; zero sums/deg; K1 -> hi/lo; K2 -> fp16 ------------------
__global__ void __launch_bounds__(256) k_prep_x(const float* __restrict__ X,
                                                const float* __restrict__ K1,
                                                const float* __restrict__ K2) {
    const int tid = threadIdx.x;
    if (blockIdx.x == 0) {
        if (tid < C0N) { d_sum1[tid] = 0.f; d_sq1[tid] = 0.f; }
        if (tid < C1N) { d_sum2[tid] = 0.f; d_sq2[tid] = 0.f; }
    }
    if (tid < 8) d_deg[blockIdx.x * 8 + tid] = 0.f;

    if (blockIdx.x < 32) {                       // K1: 32768 elems
        size_t i = ((size_t)blockIdx.x * 256 + tid) * 4;
        float4 v = *(const float4*)(K1 + i);
        float vv[4] = {v.x, v.y, v.z, v.w};
        __half h[4], l[4];
#pragma unroll
        for (int j = 0; j < 4; j++) {
            h[j] = __float2half_rn(vv[j]);
            l[j] = __float2half_rn(vv[j] - __half2float(h[j]));
        }
        *(uint2*)(d_K1h + i) = *(uint2*)h;
        *(uint2*)(d_K1l + i) = *(uint2*)l;
    } else if (blockIdx.x < 64) {                // K2: 32768 elems
        size_t i = ((size_t)(blockIdx.x - 32) * 256 + tid) * 4;
        float4 v = *(const float4*)(K2 + i);
        __half h[4];
        h[0] = __float2half_rn(v.x);
        h[1] = __float2half_rn(v.y);
        h[2] = __float2half_rn(v.z);
        h[3] = __float2half_rn(v.w);
        *(uint2*)(d_K2f + i) = *(uint2*)h;
    }

    size_t i = ((size_t)blockIdx.x * 256 + tid) * 4;
    float4 x = *(const float4*)(X + i);
    __half h[4];
    h[0] = __float2half_rn(x.x);
    h[1] = __float2half_rn(x.y);
    h[2] = __float2half_rn(x.z);
    h[3] = __float2half_rn(x.w);
    *(uint2*)(d_Xf + i) = *(uint2*)h;
}

// ============================================================================
// GEMM1: Rp[q] = A^T @ X over K quarter q.  grid (32, 4). CTA 256x128, BK=64.
// 8 warps 4M x 2N, warp 64x64.  A^T[r,k] = Adjh[k*NP + r] (col_major frags).
// ============================================================================
#define G1_LDA 264
#define G1_LDX 136
#define G1_AS_BYTES (2 * 64 * G1_LDA * 2)              // 67584
#define G1_SMEM     (G1_AS_BYTES + 2 * 64 * G1_LDX * 2) // 102400

__global__ void __launch_bounds__(256) k_gemm1() {
    extern __shared__ __align__(16) char smem_raw[];
    __half (*As)[64][G1_LDA] = (__half(*)[64][G1_LDA])smem_raw;
    __half (*Xs)[64][G1_LDX] = (__half(*)[64][G1_LDX])(smem_raw + G1_AS_BYTES);

    const int r0    = blockIdx.x * 256;
    const int kbase = blockIdx.y * KQ;
    const int tid   = threadIdx.x;
    const int warp  = tid >> 5;
    const int wm    = warp & 3;
    const int wn    = warp >> 2;

    wmma::fragment<wmma::accumulator, 16, 16, 16, float> acc[4][4];
#pragma unroll
    for (int i = 0; i < 4; i++)
#pragma unroll
        for (int j = 0; j < 4; j++) wmma::fill_fragment(acc[i][j], 0.0f);

    {
#pragma unroll
        for (int s = 0; s < 8; s++) {
            int u = tid + s * 256, kk = u >> 5, rr = (u & 31) * 8;
            cp16(&As[0][kk][rr], d_Adjh + (size_t)(kbase + kk) * NP + r0 + rr);
        }
#pragma unroll
        for (int s = 0; s < 4; s++) {
            int u = tid + s * 256, kk = u >> 4, cc = (u & 15) * 8;
            cp16(&Xs[0][kk][cc], d_Xf + (size_t)(kbase + kk) * FD + cc);
        }
        cp_commit();
    }

    const int T = KQ / 64;   // 32
    for (int t = 0; t < T; t++) {
        const int buf = t & 1;
        if (t + 1 < T) {
            const int nb = buf ^ 1;
            const int k1 = kbase + (t + 1) * 64;
#pragma unroll
            for (int s = 0; s < 8; s++) {
                int u = tid + s * 256, kk = u >> 5, rr = (u & 31) * 8;
                cp16(&As[nb][kk][rr], d_Adjh + (size_t)(k1 + kk) * NP + r0 + rr);
            }
#pragma unroll
            for (int s = 0; s < 4; s++) {
                int u = tid + s * 256, kk = u >> 4, cc = (u & 15) * 8;
                cp16(&Xs[nb][kk][cc], d_Xf + (size_t)(k1 + kk) * FD + cc);
            }
            cp_commit();
            cp_wait<1>();
        } else {
            cp_wait<0>();
        }
        __syncthreads();

#pragma unroll
        for (int ks = 0; ks < 4; ks++) {
            wmma::fragment<wmma::matrix_a, 16, 16, 16, __half, wmma::col_major> af[4];
#pragma unroll
            for (int i = 0; i < 4; i++)
                wmma::load_matrix_sync(af[i], &As[buf][ks * 16][wm * 64 + i * 16], G1_LDA);
#pragma unroll
            for (int j = 0; j < 4; j++) {
                wmma::fragment<wmma::matrix_b, 16, 16, 16, __half, wmma::row_major> bf;
                wmma::load_matrix_sync(bf, &Xs[buf][ks * 16][wn * 64 + j * 16], G1_LDX);
#pragma unroll
                for (int i = 0; i < 4; i++) wmma::mma_sync(acc[i][j], af[i], bf, acc[i][j]);
            }
        }
        __syncthreads();
    }

    float* dst = d_Rp[blockIdx.y];
#pragma unroll
    for (int i = 0; i < 4; i++)
#pragma unroll
        for (int j = 0; j < 4; j++)
            wmma::store_matrix_sync(&dst[(size_t)(r0 + wm * 64 + i * 16) * FD + wn * 64 + j * 16],
                                    acc[i][j], FD, wmma::mem_row_major);
}

// ============================================================================
// GEMM3: Op[q] = A @ R2f over K quarter q.  grid (32, 4). CTA 256x128, BK=64.
// ============================================================================
#define G3_LDA 72
#define G3_LDB 136
#define G3_AS_BYTES (2 * 256 * G3_LDA * 2)             // 73728
#define G3_SMEM     (G3_AS_BYTES + 2 * 64 * G3_LDB * 2) // 108544

__global__ void __launch_bounds__(256) k_gemm3() {
    extern __shared__ __align__(16) char smem_raw[];
    __half (*As)[256][G3_LDA] = (__half(*)[256][G3_LDA])smem_raw;
    __half (*Bs)[64][G3_LDB]  = (__half(*)[64][G3_LDB])(smem_raw + G3_AS_BYTES);

    const int p0    = blockIdx.x * 256;
    const int kbase = blockIdx.y * KQ;
    const int tid   = threadIdx.x;
    const int warp  = tid >> 5;
    const int wm    = warp & 3;
    const int wn    = warp >> 2;

    wmma::fragment<wmma::accumulator, 16, 16, 16, float> acc[4][4];
#pragma unroll
    for (int i = 0; i < 4; i++)
#pragma unroll
        for (int j = 0; j < 4; j++) wmma::fill_fragment(acc[i][j], 0.0f);

    {
#pragma unroll
        for (int s = 0; s < 8; s++) {
            int u = tid + s * 256, pp = u >> 3, kc = (u & 7) * 8;
            cp16(&As[0][pp][kc], d_Adjh + (size_t)(p0 + pp) * NP + kbase + kc);
        }
#pragma unroll
        for (int s = 0; s < 4; s++) {
            int u = tid + s * 256, kk = u >> 4, cc = (u & 15) * 8;
            cp16(&Bs[0][kk][cc], d_R2f + (size_t)(kbase + kk) * C1N + cc);
        }
        cp_commit();
    }

    const int T = KQ / 64;
    for (int t = 0; t < T; t++) {
        const int buf = t & 1;
        if (t + 1 < T) {
            const int nb = buf ^ 1;
            const int k1 = kbase + (t + 1) * 64;
#pragma unroll
            for (int s = 0; s < 8; s++) {
                int u = tid + s * 256, pp = u >> 3, kc = (u & 7) * 8;
                cp16(&As[nb][pp][kc], d_Adjh + (size_t)(p0 + pp) * NP + k1 + kc);
            }
#pragma unroll
            for (int s = 0; s < 4; s++) {
                int u = tid + s * 256, kk = u >> 4, cc = (u & 15) * 8;
                cp16(&Bs[nb][kk][cc], d_R2f + (size_t)(k1 + kk) * C1N + cc);
            }
            cp_commit();
            cp_wait<1>();
        } else {
            cp_wait<0>();
        }
        __syncthreads();

#pragma unroll
        for (int ks = 0; ks < 4; ks++) {
            wmma::fragment<wmma::matrix_a, 16, 16, 16, __half, wmma::row_major> af[4];
#pragma unroll
            for (int i = 0; i < 4; i++)
                wmma::load_matrix_sync(af[i], &As[buf][wm * 64 + i * 16][ks * 16], G3_LDA);
#pragma unroll
            for (int j = 0; j < 4; j++) {
                wmma::fragment<wmma::matrix_b, 16, 16, 16, __half, wmma::row_major> bf;
                wmma::load_matrix_sync(bf, &Bs[buf][ks * 16][wn * 64 + j * 16], G3_LDB);
#pragma unroll
                for (int i = 0; i < 4; i++) wmma::mma_sync(acc[i][j], af[i], bf, acc[i][j]);
            }
        }
        __syncthreads();
    }

    float* dst = d_Op[blockIdx.y];
#pragma unroll
    for (int i = 0; i < 4; i++)
#pragma unroll
        for (int j = 0; j < 4; j++)
            wmma::store_matrix_sync(&dst[(size_t)(p0 + wm * 64 + i * 16) * C1N + wn * 64 + j * 16],
                                    acc[i][j], C1N, wmma::mem_row_major);
}

// --------- prep: sum(Rp) -> hi/lo fp16 (pure, full-width) --------------------
__global__ void __launch_bounds__(256) k_prep_rpre() {
    size_t i = ((size_t)blockIdx.x * 256 + threadIdx.x) * 4;
    float4 a = *(const float4*)(d_Rp[0] + i);
    float4 b = *(const float4*)(d_Rp[1] + i);
    float4 c = *(const float4*)(d_Rp[2] + i);
    float4 d = *(const float4*)(d_Rp[3] + i);
    float vv[4] = {a.x + b.x + c.x + d.x, a.y + b.y + c.y + d.y,
                   a.z + b.z + c.z + d.z, a.w + b.w + c.w + d.w};
    __half h[4], l[4];
#pragma unroll
    for (int j = 0; j < 4; j++) {
        h[j] = __float2half_rn(vv[j]);
        l[j] = __float2half_rn(vv[j] - __half2float(h[j]));
    }
    *(uint2*)(d_RpH + i) = *(uint2*)h;
    *(uint2*)(d_RpL + i) = *(uint2*)l;
}

// ============================================================================
// small_h (tensor, 3-term hi/lo): H = invdeg*(Rp@K1)+b1, fused BN1 stats.
// grid (128, 2): M-tile 64, N-tile 128, K=128 single shot.
// ============================================================================
#define SH_LDA 136
#define SH_LDB 136
#define SH_A_BYTES (64 * SH_LDA * 2)
#define SH_B_BYTES (128 * SH_LDB * 2)
#define SH_SMEM    (2 * SH_A_BYTES + 2 * SH_B_BYTES)   // 104448
#define SH_LDC 132

__global__ void __launch_bounds__(256) k_small_h_tc(const float* __restrict__ bias) {
    extern __shared__ __align__(16) char sm[];
    __half (*Ah)[SH_LDA] = (__half(*)[SH_LDA])sm;
    __half (*Al)[SH_LDA] = (__half(*)[SH_LDA])(sm + SH_A_BYTES);
    __half (*Bh)[SH_LDB] = (__half(*)[SH_LDB])(sm + 2 * SH_A_BYTES);
    __half (*Bl)[SH_LDB] = (__half(*)[SH_LDB])(sm + 2 * SH_A_BYTES + SH_B_BYTES);
    float  (*Ct)[SH_LDC] = (float(*)[SH_LDC])sm;

    const int m0  = blockIdx.x * 64;
    const int n0  = blockIdx.y * 128;
    const int tid = threadIdx.x;
    const int warp = tid >> 5;
    const int wm   = warp & 1;
    const int wn   = warp >> 1;

#pragma unroll
    for (int s = 0; s < 4; s++) {
        int u = tid + s * 256, row = u >> 4, col = (u & 15) * 8;
        cp16(&Ah[row][col], d_RpH + (size_t)(m0 + row) * FD + col);
        cp16(&Al[row][col], d_RpL + (size_t)(m0 + row) * FD + col);
    }
#pragma unroll
    for (int s = 0; s < 8; s++) {
        int u = tid + s * 256, kk = u >> 4, cc = (u & 15) * 8;
        cp16(&Bh[kk][cc], d_K1h + (size_t)kk * C0N + n0 + cc);
        cp16(&Bl[kk][cc], d_K1l + (size_t)kk * C0N + n0 + cc);
    }
    cp_commit();
    cp_wait<0>();
    __syncthreads();

    wmma::fragment<wmma::accumulator, 16, 16, 16, float> acc[2][2];
#pragma unroll
    for (int i = 0; i < 2; i++)
#pragma unroll
        for (int j = 0; j < 2; j++) wmma::fill_fragment(acc[i][j], 0.0f);

#pragma unroll
    for (int ks = 0; ks < 8; ks++) {
        wmma::fragment<wmma::matrix_a, 16, 16, 16, __half, wmma::row_major> afh[2], afl[2];
#pragma unroll
        for (int i = 0; i < 2; i++) {
            wmma::load_matrix_sync(afh[i], &Ah[wm * 32 + i * 16][ks * 16], SH_LDA);
            wmma::load_matrix_sync(afl[i], &Al[wm * 32 + i * 16][ks * 16], SH_LDA);
        }
        wmma::fragment<wmma::matrix_b, 16, 16, 16, __half, wmma::row_major> bfh[2], bfl[2];
#pragma unroll
        for (int j = 0; j < 2; j++) {
            wmma::load_matrix_sync(bfh[j], &Bh[ks * 16][wn * 32 + j * 16], SH_LDB);
            wmma::load_matrix_sync(bfl[j], &Bl[ks * 16][wn * 32 + j * 16], SH_LDB);
        }
#pragma unroll
        for (int j = 0; j < 2; j++)
#pragma unroll
            for (int i = 0; i < 2; i++) {
                wmma::mma_sync(acc[i][j], afh[i], bfh[j], acc[i][j]);
                wmma::mma_sync(acc[i][j], afh[i], bfl[j], acc[i][j]);
                wmma::mma_sync(acc[i][j], afl[i], bfh[j], acc[i][j]);
            }
    }
    __syncthreads();

#pragma unroll
    for (int i = 0; i < 2; i++)
#pragma unroll
        for (int j = 0; j < 2; j++)
            wmma::store_matrix_sync(&Ct[wm * 32 + i * 16][wn * 32 + j * 16],
                                    acc[i][j], SH_LDC, wmma::mem_row_major);
    __syncthreads();

    {
        const int c    = tid & 127;
        const int half = tid >> 7;
        const float b  = bias[n0 + c];
        float s = 0.f, q = 0.f;
#pragma unroll 8
        for (int r = half * 32; r < half * 32 + 32; r++) {
            int gr = m0 + r;
            float dg = d_deg[gr];
            float idg = (dg > 0.5f) ? (1.0f / dg) : 0.0f;
            float v = Ct[r][c] * idg + b;
            d_H[(size_t)gr * C0N + n0 + c] = v;
            s += v;
            q = fmaf(v, v, q);
        }
        atomicAdd(&d_sum1[n0 + c], s);
        atomicAdd(&d_sq1[n0 + c], q);
    }
}

// ============================================================================
// small_r2 (tensor, fused fin1 + affine-on-load): R2f = fp16(4096*invdeg*
// BN1(H)) @ K2f.  grid 128: M-tile 64, N=128 full, K=256 single shot.
// ============================================================================
#define SR_LDA 264
#define SR_LDB 136
#define SR_A_BYTES (64 * SR_LDA * 2)
#define SR_B_BYTES (256 * SR_LDB * 2)
#define SR_SMEM    (SR_A_BYTES + SR_B_BYTES)   // 103424
#define SR_LDC 132

__global__ void __launch_bounds__(256) k_small_r2_tc(const float* __restrict__ gamma,
                                                     const float* __restrict__ beta) {
    extern __shared__ __align__(16) char sm[];
    __half (*As)[SR_LDA] = (__half(*)[SR_LDA])sm;
    __half (*Bs)[SR_LDB] = (__half(*)[SR_LDB])(sm + SR_A_BYTES);
    float  (*Ct)[SR_LDC] = (float(*)[SR_LDC])sm;
    __shared__ float ssc[C0N], ssh[C0N], sidg[64];

    const int m0  = blockIdx.x * 64;
    const int tid = threadIdx.x;
    const int warp = tid >> 5;
    const int wm   = warp & 1;
    const int wn   = warp >> 1;

    // B tile via cp.async (overlaps with fin1 + A affine)
#pragma unroll
    for (int s = 0; s < 16; s++) {
        int u = tid + s * 256, kk = u >> 4, cc = (u & 15) * 8;
        cp16(&Bs[kk][cc], d_K2f + (size_t)kk * C1N + cc);
    }
    cp_commit();

    // fin1 (redundant per block) + scaled invdeg for this M-tile
    {
        float mean = d_sum1[tid] * (1.0f / NP);
        float var  = d_sq1[tid] * (1.0f / NP) - mean * mean;
        float sc   = gamma[tid] * rsqrtf(var + BN_EPS);
        ssc[tid] = sc;
        ssh[tid] = beta[tid] - mean * sc;
    }
    if (tid < 64) {
        float dg = d_deg[m0 + tid];
        sidg[tid] = (dg > 0.5f) ? (4096.0f / dg) : 0.0f;
    }
    __syncthreads();

    // A tile: LDG H fp32 -> affine*idg -> fp16 -> STS
#pragma unroll
    for (int s = 0; s < 16; s++) {
        int u = tid + s * 256, row = u >> 6, col = (u & 63) * 4;
        float4 h4 = *(const float4*)(d_H + (size_t)(m0 + row) * C0N + col);
        float idg = sidg[row];
        __half o[4];
        o[0] = __float2half_rn(idg * fmaf(h4.x, ssc[col + 0], ssh[col + 0]));
        o[1] = __float2half_rn(idg * fmaf(h4.y, ssc[col + 1], ssh[col + 1]));
        o[2] = __float2half_rn(idg * fmaf(h4.z, ssc[col + 2], ssh[col + 2]));
        o[3] = __float2half_rn(idg * fmaf(h4.w, ssc[col + 3], ssh[col + 3]));
        *(uint2*)&As[row][col] = *(uint2*)o;
    }
    cp_wait<0>();
    __syncthreads();

    wmma::fragment<wmma::accumulator, 16, 16, 16, float> acc[2][2];
#pragma unroll
    for (int i = 0; i < 2; i++)
#pragma unroll
        for (int j = 0; j < 2; j++) wmma::fill_fragment(acc[i][j], 0.0f);

#pragma unroll
    for (int ks = 0; ks < 16; ks++) {
        wmma::fragment<wmma::matrix_a, 16, 16, 16, __half, wmma::row_major> af[2];
#pragma unroll
        for (int i = 0; i < 2; i++)
            wmma::load_matrix_sync(af[i], &As[wm * 32 + i * 16][ks * 16], SR_LDA);
        wmma::fragment<wmma::matrix_b, 16, 16, 16, __half, wmma::row_major> bf[2];
#pragma unroll
        for (int j = 0; j < 2; j++)
            wmma::load_matrix_sync(bf[j], &Bs[ks * 16][wn * 32 + j * 16], SR_LDB);
#pragma unroll
        for (int j = 0; j < 2; j++)
#pragma unroll
            for (int i = 0; i < 2; i++) wmma::mma_sync(acc[i][j], af[i], bf[j], acc[i][j]);
    }
    __syncthreads();

#pragma unroll
    for (int i = 0; i < 2; i++)
#pragma unroll
        for (int j = 0; j < 2; j++)
            wmma::store_matrix_sync(&Ct[wm * 32 + i * 16][wn * 32 + j * 16],
                                    acc[i][j], SR_LDC, wmma::mem_row_major);
    __syncthreads();

    {
        const int c    = tid & 127;
        const int half = tid >> 7;
#pragma unroll 8
        for (int r = half * 32; r < half * 32 + 32; r++)
            d_R2f[(size_t)(m0 + r) * C1N + c] = __float2half_rn(Ct[r][c]);
    }
}

// ------------- combine O partials (undo 4096 scale) + bias, BN2 stats --------
__global__ void __launch_bounds__(128) k_stats2(const float* __restrict__ bias2) {
    const int c  = threadIdx.x;
    const int r0 = blockIdx.x * 64;
    const float b = bias2[c];
    const float inv = 1.0f / 4096.0f;
    float s = 0.f, q = 0.f;
#pragma unroll 4
    for (int r = r0; r < r0 + 64; r++) {
        size_t idx = (size_t)r * C1N + c;
        float v = (d_Op[0][idx] + d_Op[1][idx] + d_Op[2][idx] + d_Op[3][idx]) * inv + b;
        d_O[idx] = v;
        s += v;
        q = fmaf(v, v, q);
    }
    atomicAdd(&d_sum2[c], s);
    atomicAdd(&d_sq2[c], q);
}

// ---------------- output with fin2 inlined -----------------------------------
__global__ void __launch_bounds__(256) k_out(const float* __restrict__ gamma,
                                             const float* __restrict__ beta,
                                             float* __restrict__ out) {
    __shared__ float ssc[C1N], ssh[C1N];
    const int tid = threadIdx.x;
    if (tid < C1N) {
        float mean = d_sum2[tid] * (1.0f / NP);
        float var  = d_sq2[tid] * (1.0f / NP) - mean * mean;
        float sc   = gamma[tid] * rsqrtf(var + BN_EPS);
        ssc[tid] = sc;
        ssh[tid] = beta[tid] - mean * sc;
    }
    __syncthreads();
    size_t i = ((size_t)blockIdx.x * 256 + tid) * 4;
    int c = (int)(i & (C1N - 1));
    float4 v = *(const float4*)(d_O + i);
    float4 o;
    o.x = fmaf(v.x, ssc[c + 0], ssh[c + 0]);
    o.y = fmaf(v.y, ssc[c + 1], ssh[c + 1]);
    o.z = fmaf(v.z, ssc[c + 2], ssh[c + 2]);
    o.w = fmaf(v.w, ssc[c + 3], ssh[c + 3]);
    *(float4*)(out + i) = o;
}

// ---------------- launch ----------------------------------------------------
extern "C" void kernel_launch(void* const* d_in, const int* in_sizes, int n_in,
                              void* d_out, int out_size) {
    const float* features = (const float*)d_in[0];
    const int*   adj      = (const int*)d_in[1];
    const float* kernel_1 = (const float*)d_in[2];
    const float* bias_1   = (const float*)d_in[3];
    const float* gamma_1  = (const float*)d_in[4];
    const float* beta_1   = (const float*)d_in[5];
    const float* kernel_2 = (const float*)d_in[6];
    const float* bias_2   = (const float*)d_in[7];
    const float* gamma_2  = (const float*)d_in[8];
    const float* beta_2   = (const float*)d_in[9];
    float* out = (float*)d_out;

    cudaFuncSetAttribute(k_gemm1, cudaFuncAttributeMaxDynamicSharedMemorySize, G1_SMEM);
    cudaFuncSetAttribute(k_gemm3, cudaFuncAttributeMaxDynamicSharedMemorySize, G3_SMEM);
    cudaFuncSetAttribute(k_small_h_tc, cudaFuncAttributeMaxDynamicSharedMemorySize, SH_SMEM);
    cudaFuncSetAttribute(k_small_r2_tc, cudaFuncAttributeMaxDynamicSharedMemorySize, SR_SMEM);

    k_prep_x<<<NP * FD / (256 * 4), 256>>>(features, kernel_1, kernel_2); // X/K1/K2 + zero
    k_prep_adj<<<dim3(NP / 128, NP / 128), 256>>>(adj);                   // adj fp16 + degree
    k_gemm1<<<dim3(NP / 256, KSPLIT), 256, G1_SMEM>>>();                  // Rpre partials
    k_prep_rpre<<<NP * FD / (256 * 4), 256>>>();                          // sum + hi/lo split
    k_small_h_tc<<<dim3(NP / 64, C0N / 128), 256, SH_SMEM>>>(bias_1);     // H + stats1
    k_small_r2_tc<<<NP / 64, 256, SR_SMEM>>>(gamma_1, beta_1);            // fin1 + Rs + R2f
    k_gemm3<<<dim3(NP / 256, KSPLIT), 256, G3_SMEM>>>();                  // O partials
    k_stats2<<<NP / 64, 128>>>(bias_2);                                   // combine + stats2
    k_out<<<NP * C1N / (256 * 4), 256>>>(gamma_2, beta_2, out);           // fin2 + out
}